// round 13
// baseline (speedup 1.0000x reference)
#include <cuda_runtime.h>
#include <cuda_fp16.h>
#include <math.h>
#include <stdint.h>

// LTCAttentionCell — round 13: R12 minus the combined-matrix scratch round trip.
// Main kernel loads fp32 x_t/h_ltc/context directly (L2-resident), converts to
// fp16 inline in the A-loader (LDG.128 -> cvt -> STS.128). Prep = weights only.
// Main GEMM loop is at the legacy-HMMA issue floor (R12: 255K cyc @ ~2GHz).

#define IN_DIM 128
#define HID    512
#define ATT    256
#define KTOT   896
#define BROWS  16384

#define BM 128
#define BN 64
#define KBLK 128
#define NCH (KTOT / KBLK)        // 7
#define NTH 512
#define A_SZ  32768              // 128 rows x 256B (fp16)
#define B_SZ  16384              // 64 rows x 256B
#define STAGE_BYTES (A_SZ + 3 * B_SZ)        // 81920
#define SMEM_DYN (2 * STAGE_BYTES + 128)     // ~160K

__device__ __half g_wgd [(size_t)1024 * KTOT];
__device__ __half g_wtau[(size_t)512  * HID];

__device__ __forceinline__ uint32_t s2u(const void* p) {
    return (uint32_t)__cvta_generic_to_shared(p);
}
__device__ __forceinline__ void cp16(uint32_t dst, const void* src) {
    asm volatile("cp.async.cg.shared.global [%0], [%1], 16;" :: "r"(dst), "l"(src));
}
__device__ __forceinline__ void cp_commit() {
    asm volatile("cp.async.commit_group;" ::: "memory");
}
template<int N> __device__ __forceinline__ void cp_wait() {
    asm volatile("cp.async.wait_group %0;" :: "n"(N) : "memory");
}
__device__ __forceinline__ void ldm_x4(uint32_t* d, uint32_t addr) {
    asm volatile("ldmatrix.sync.aligned.m8n8.x4.shared.b16 {%0,%1,%2,%3}, [%4];"
                 : "=r"(d[0]), "=r"(d[1]), "=r"(d[2]), "=r"(d[3]) : "r"(addr));
}
__device__ __forceinline__ void mma_f16(float* c, const uint32_t* a, uint32_t b0, uint32_t b1) {
    asm volatile("mma.sync.aligned.m16n8k16.row.col.f32.f16.f16.f32 "
                 "{%0,%1,%2,%3}, {%4,%5,%6,%7}, {%8,%9}, {%0,%1,%2,%3};"
                 : "+f"(c[0]), "+f"(c[1]), "+f"(c[2]), "+f"(c[3])
                 : "r"(a[0]), "r"(a[1]), "r"(a[2]), "r"(a[3]), "r"(b0), "r"(b1));
}
__device__ __forceinline__ void sts128(uint32_t addr, uint32_t x, uint32_t y,
                                       uint32_t z, uint32_t w) {
    asm volatile("st.shared.v4.b32 [%0], {%1,%2,%3,%4};"
                 :: "r"(addr), "r"(x), "r"(y), "r"(z), "r"(w) : "memory");
}

// ---- fast-math activations (err ~1e-6 << 1.7e-4 fp16 floor) ----
__device__ __forceinline__ float softplus_fast(float x) {
    return (x > 20.0f) ? x : __logf(1.0f + __expf(x));
}
__device__ __forceinline__ float sigmoid_fast(float x) {
    return __fdividef(1.0f, 1.0f + __expf(-x));
}
__device__ __forceinline__ float tanh_fast(float x) {
    return 1.0f - __fdividef(2.0f, __expf(2.0f * x) + 1.0f);
}

// 256B rows = 16x16B chunks; swizzle low 3 bits of chunk with row&7
__device__ __forceinline__ uint32_t sw256(int row, int k) {
    int ch = k >> 3;
    int swc = ((ch & 7) ^ (row & 7)) | (ch & 8);
    return row * 256 + ((swc << 4) | ((k & 7) * 2));
}

// convert 8 fp32 -> 4x uint32 (half2 pairs)
__device__ __forceinline__ void cvt8_regs(float4 v0, float4 v1, uint32_t* o) {
    __half2 h0 = __floats2half2_rn(v0.x, v0.y);
    __half2 h1 = __floats2half2_rn(v0.z, v0.w);
    __half2 h2 = __floats2half2_rn(v1.x, v1.y);
    __half2 h3 = __floats2half2_rn(v1.z, v1.w);
    o[0] = *reinterpret_cast<uint32_t*>(&h0);
    o[1] = *reinterpret_cast<uint32_t*>(&h1);
    o[2] = *reinterpret_cast<uint32_t*>(&h2);
    o[3] = *reinterpret_cast<uint32_t*>(&h3);
}

// ---------------- pre-pass: weights only ----------------
__device__ __forceinline__ void cvt8(const float* src, __half* dst) {
    float4 v0 = *reinterpret_cast<const float4*>(src);
    float4 v1 = *reinterpret_cast<const float4*>(src + 4);
    uint32_t o[4];
    cvt8_regs(v0, v1, o);
    uint4 u; u.x = o[0]; u.y = o[1]; u.z = o[2]; u.w = o[3];
    *reinterpret_cast<uint4*>(dst) = u;
}

__global__ void __launch_bounds__(256)
prep_weights(const float* __restrict__ W_gd, const float* __restrict__ W_tau)
{
    int idx = blockIdx.x * 256 + threadIdx.x;   // 114688 + 32768 threads
    if (idx < 114688) {
        int row = idx / 112;
        int j = (idx - row * 112) * 8;
        cvt8(&W_gd[(size_t)row * KTOT + j], &g_wgd[(size_t)row * KTOT + j]);
    } else {
        int e = idx - 114688;
        int row = e >> 6;
        int j = (e & 63) * 8;
        cvt8(&W_tau[(size_t)row * HID + j], &g_wtau[(size_t)row * HID + j]);
    }
}

// ---------------- main kernel ----------------
__global__ void __launch_bounds__(NTH, 1)
ltc_f16_kernel(const float* __restrict__ h_ltc, const float* __restrict__ x_t,
               const float* __restrict__ context,
               const float* __restrict__ b_gd, const float* __restrict__ b_tau,
               const float* __restrict__ gleak, const float* __restrict__ cm,
               float* __restrict__ out)
{
    extern __shared__ char smem[];
    const uint32_t data = (s2u(smem) + 127) & ~127u;

    const int tid  = threadIdx.x;
    const int wid  = tid >> 5;
    const int lane = tid & 31;
    const int m0 = blockIdx.y * BM;
    const int n0 = blockIdx.x * BN;

    const int wm = (wid & 3) * 32;    // 4 m-warps x 4 n-warps, warp tile 32x16
    const int wn = (wid >> 2) * 16;

    const int a_row = ((lane >> 3) & 1) * 8 + (lane & 7);
    const int a_k   = ((lane >> 4) & 1) * 8;
    const int b_row = ((lane >> 4) & 1) * 8 + (lane & 7);
    const int b_k   = ((lane >> 3) & 1) * 8;

    // LDSM offsets for ks 0..3; ks+4 = +128 bytes
    uint32_t aoff[2][4], bgof[4];
#pragma unroll
    for (int ks = 0; ks < 4; ++ks) {
#pragma unroll
        for (int mb = 0; mb < 2; ++mb)
            aoff[mb][ks] = sw256(wm + mb * 16 + a_row, ks * 16 + a_k);
        bgof[ks] = A_SZ + sw256(wn + b_row, ks * 16 + b_k);
    }

    // A loader: slot i handles fp16 row r0+32i, 16B-chunk ch (8 halves).
    const int r0 = tid >> 4;          // 0..31
    const int ach = tid & 15;         // cols ach*8 .. ach*8+7
    uint32_t dAo[4];
#pragma unroll
    for (int i = 0; i < 4; ++i) dAo[i] = sw256(r0 + 32 * i, ach * 8);

    // B loader (cp.async, fp16 scratch)
    uint32_t dBo[2]; const __half *srcG[2], *srcD[2], *srcT[2];
#pragma unroll
    for (int i = 0; i < 2; ++i) {
        int s = tid + i * 512, r = s >> 4, ch = s & 15;
        dBo[i] = sw256(r, ch * 8);
        srcG[i] = g_wgd  + (size_t)(n0 + r) * KTOT + ch * 8;
        srcD[i] = g_wgd  + (size_t)(HID + n0 + r) * KTOT + ch * 8;
        srcT[i] = g_wtau + (size_t)(n0 + r) * HID + ch * 8;
    }

    float accg[2][2][4] = {}, accd[2][2][4] = {}, acct[2][2][4] = {};

    // chunk c -> fp32 source of combined cols [c*128, c*128+128)
    auto load_chunk = [&](int c, uint32_t st) {
        // ---- B via cp.async ----
#pragma unroll
        for (int i = 0; i < 2; ++i) {
            cp16(st + A_SZ + dBo[i],        srcG[i] + c * KBLK);
            cp16(st + A_SZ + B_SZ + dBo[i], srcD[i] + c * KBLK);
        }
        if (c >= 1 && c < 5) {
#pragma unroll
            for (int i = 0; i < 2; ++i)
                cp16(st + A_SZ + 2 * B_SZ + dBo[i], srcT[i] + (c - 1) * KBLK);
        }
        cp_commit();

        // ---- A: fp32 LDG -> cvt -> STS (sources L2-resident) ----
        const float* src; int stride, col0;
        if (c == 0)      { src = x_t;     stride = IN_DIM; col0 = 0; }
        else if (c < 5)  { src = h_ltc;   stride = HID;    col0 = (c - 1) * 128; }
        else             { src = context; stride = ATT;    col0 = (c - 5) * 128; }
        const float* base = src + (size_t)(m0 + r0) * stride + col0 + ach * 8;
        const size_t rstep = (size_t)32 * stride;
        // slot-pairwise to bound staging registers
#pragma unroll
        for (int p = 0; p < 2; ++p) {
            float4 v0a = *reinterpret_cast<const float4*>(base + (2 * p + 0) * rstep);
            float4 v1a = *reinterpret_cast<const float4*>(base + (2 * p + 0) * rstep + 4);
            float4 v0b = *reinterpret_cast<const float4*>(base + (2 * p + 1) * rstep);
            float4 v1b = *reinterpret_cast<const float4*>(base + (2 * p + 1) * rstep + 4);
            uint32_t oa[4], ob[4];
            cvt8_regs(v0a, v1a, oa);
            cvt8_regs(v0b, v1b, ob);
            sts128(st + dAo[2 * p + 0], oa[0], oa[1], oa[2], oa[3]);
            sts128(st + dAo[2 * p + 1], ob[0], ob[1], ob[2], ob[3]);
        }
    };

    auto compute = [&](uint32_t st, bool tau_act) {
#pragma unroll
        for (int k8 = 0; k8 < 8; ++k8) {
            const int ks = k8 & 3;
            const uint32_t ext = (k8 >> 2) * 128;
            uint32_t a[2][4];
            ldm_x4(a[0], st + aoff[0][ks] + ext);
            ldm_x4(a[1], st + aoff[1][ks] + ext);
            uint32_t bg[4], bd[4], bt[4];
            const uint32_t bga = st + bgof[ks] + ext;
            ldm_x4(bg, bga);
            ldm_x4(bd, bga + B_SZ);
            if (tau_act) ldm_x4(bt, bga + 2 * B_SZ);
#pragma unroll
            for (int mb = 0; mb < 2; ++mb)
#pragma unroll
                for (int nb = 0; nb < 2; ++nb) {
                    mma_f16(accg[mb][nb], a[mb], bg[nb * 2], bg[nb * 2 + 1]);
                    mma_f16(accd[mb][nb], a[mb], bd[nb * 2], bd[nb * 2 + 1]);
                }
            if (tau_act) {
#pragma unroll
                for (int mb = 0; mb < 2; ++mb)
#pragma unroll
                    for (int nb = 0; nb < 2; ++nb)
                        mma_f16(acct[mb][nb], a[mb], bt[nb * 2], bt[nb * 2 + 1]);
            }
        }
    };

    const uint32_t st0 = data;
    const uint32_t st1 = data + STAGE_BYTES;

    // chunks: c=0 (x_t), c=1..4 (h_ltc, tau active), c=5,6 (context). stage = c&1.
    load_chunk(0, st0);
    __syncthreads();               // A STS of chunk 0 visible

    cp_wait<0>(); __syncthreads();
    load_chunk(1, st1);
    compute(st0, false);          // c=0

    cp_wait<0>(); __syncthreads();
    load_chunk(2, st0);
    compute(st1, true);           // c=1

    cp_wait<0>(); __syncthreads();
    load_chunk(3, st1);
    compute(st0, true);           // c=2

    cp_wait<0>(); __syncthreads();
    load_chunk(4, st0);
    compute(st1, true);           // c=3

    cp_wait<0>(); __syncthreads();
    load_chunk(5, st1);
    compute(st0, true);           // c=4

    cp_wait<0>(); __syncthreads();
    load_chunk(6, st0);
    compute(st1, false);          // c=5

    cp_wait<0>(); __syncthreads();
    compute(st0, false);          // c=6

    // ---- fused epilogue (fast math) ----
    const int g  = lane >> 2;
    const int c2 = (lane & 3) * 2;
#pragma unroll
    for (int mb = 0; mb < 2; ++mb)
#pragma unroll
        for (int nb = 0; nb < 2; ++nb) {
            const int n = n0 + wn + nb * 8 + c2;
            const float bg0 = __ldg(&b_gd[n]),        bg1 = __ldg(&b_gd[n + 1]);
            const float bd0 = __ldg(&b_gd[n + HID]),  bd1 = __ldg(&b_gd[n + HID + 1]);
            const float bt0 = __ldg(&b_tau[n]),       bt1 = __ldg(&b_tau[n + 1]);
            const float dc0 = softplus_fast(__ldg(&cm[n]))   + softplus_fast(__ldg(&gleak[n]))   + 1e-6f;
            const float dc1 = softplus_fast(__ldg(&cm[n+1])) + softplus_fast(__ldg(&gleak[n+1])) + 1e-6f;
#pragma unroll
            for (int h = 0; h < 2; ++h) {
                const int m = m0 + wm + mb * 16 + h * 8 + g;
                const float2 hl = *reinterpret_cast<const float2*>(&h_ltc[(size_t)m * HID + n]);

                float gate0 = accg[mb][nb][h * 2 + 0] + bg0;
                float gate1 = accg[mb][nb][h * 2 + 1] + bg1;
                float dyn0  = accd[mb][nb][h * 2 + 0] + bd0;
                float dyn1  = accd[mb][nb][h * 2 + 1] + bd1;
                float tau0  = softplus_fast(acct[mb][nb][h * 2 + 0] + bt0);
                float tau1  = softplus_fast(acct[mb][nb][h * 2 + 1] + bt1);

                float r0 = __fdividef(sigmoid_fast(gate0) * tanh_fast(dyn0) - hl.x, tau0 + dc0);
                float r1 = __fdividef(sigmoid_fast(gate1) * tanh_fast(dyn1) - hl.y, tau1 + dc1);

                float2 o; o.x = r0; o.y = r1;
                *reinterpret_cast<float2*>(&out[(size_t)m * HID + n]) = o;
            }
        }
}

extern "C" void kernel_launch(void* const* d_in, const int* in_sizes, int n_in,
                              void* d_out, int out_size)
{
    // input order: t, h_ltc, x_t, context, W_gd, b_gd, W_tau, b_tau, gleak, cm
    const float* h_ltc   = (const float*)d_in[1];
    const float* x_t     = (const float*)d_in[2];
    const float* context = (const float*)d_in[3];
    const float* W_gd    = (const float*)d_in[4];
    const float* b_gd    = (const float*)d_in[5];
    const float* W_tau   = (const float*)d_in[6];
    const float* b_tau   = (const float*)d_in[7];
    const float* gleak   = (const float*)d_in[8];
    const float* cm      = (const float*)d_in[9];
    float* out = (float*)d_out;

    cudaFuncSetAttribute(ltc_f16_kernel,
                         cudaFuncAttributeMaxDynamicSharedMemorySize, SMEM_DYN);

    prep_weights<<<576, 256>>>(W_gd, W_tau);   // 147456 threads

    dim3 grid(HID / BN, BROWS / BM);   // (8, 128)
    ltc_f16_kernel<<<grid, NTH, SMEM_DYN>>>(h_ltc, x_t, context,
                                            b_gd, b_tau, gleak, cm, out);
}

// round 14
// speedup vs baseline: 1.1030x; 1.1030x over previous
#include <cuda_runtime.h>
#include <cuda_fp16.h>
#include <math.h>
#include <stdint.h>

// LTCAttentionCell — round 14: eliminate the combined-matrix scratch (R13 goal)
// with R12's latency discipline: A fp32 loads are issued as LDGs, covered by
// two k8 MMA groups, then cvt+STS into the next stage. 8 floats staged at a
// time. B via cp.async (unchanged). Prep = weights only (~2us).

#define IN_DIM 128
#define HID    512
#define ATT    256
#define KTOT   896
#define BROWS  16384

#define BM 128
#define BN 64
#define KBLK 128
#define NTH 512
#define A_SZ  32768              // 128 rows x 256B (fp16)
#define B_SZ  16384              // 64 rows x 256B
#define STAGE_BYTES (A_SZ + 3 * B_SZ)        // 81920
#define SMEM_DYN (2 * STAGE_BYTES + 128)     // ~160K

__device__ __half g_wgd [(size_t)1024 * KTOT];
__device__ __half g_wtau[(size_t)512  * HID];

__device__ __forceinline__ uint32_t s2u(const void* p) {
    return (uint32_t)__cvta_generic_to_shared(p);
}
__device__ __forceinline__ void cp16(uint32_t dst, const void* src) {
    asm volatile("cp.async.cg.shared.global [%0], [%1], 16;" :: "r"(dst), "l"(src));
}
__device__ __forceinline__ void cp_commit() {
    asm volatile("cp.async.commit_group;" ::: "memory");
}
template<int N> __device__ __forceinline__ void cp_wait() {
    asm volatile("cp.async.wait_group %0;" :: "n"(N) : "memory");
}
__device__ __forceinline__ void ldm_x4(uint32_t* d, uint32_t addr) {
    asm volatile("ldmatrix.sync.aligned.m8n8.x4.shared.b16 {%0,%1,%2,%3}, [%4];"
                 : "=r"(d[0]), "=r"(d[1]), "=r"(d[2]), "=r"(d[3]) : "r"(addr));
}
__device__ __forceinline__ void mma_f16(float* c, const uint32_t* a, uint32_t b0, uint32_t b1) {
    asm volatile("mma.sync.aligned.m16n8k16.row.col.f32.f16.f16.f32 "
                 "{%0,%1,%2,%3}, {%4,%5,%6,%7}, {%8,%9}, {%0,%1,%2,%3};"
                 : "+f"(c[0]), "+f"(c[1]), "+f"(c[2]), "+f"(c[3])
                 : "r"(a[0]), "r"(a[1]), "r"(a[2]), "r"(a[3]), "r"(b0), "r"(b1));
}
__device__ __forceinline__ void sts128(uint32_t addr, const uint32_t* o) {
    asm volatile("st.shared.v4.b32 [%0], {%1,%2,%3,%4};"
                 :: "r"(addr), "r"(o[0]), "r"(o[1]), "r"(o[2]), "r"(o[3]) : "memory");
}

// ---- fast-math activations (err ~1e-6 << 1.7e-4 fp16 floor) ----
__device__ __forceinline__ float softplus_fast(float x) {
    return (x > 20.0f) ? x : __logf(1.0f + __expf(x));
}
__device__ __forceinline__ float sigmoid_fast(float x) {
    return __fdividef(1.0f, 1.0f + __expf(-x));
}
__device__ __forceinline__ float tanh_fast(float x) {
    return 1.0f - __fdividef(2.0f, __expf(2.0f * x) + 1.0f);
}

// 256B rows = 16x16B chunks; swizzle low 3 bits of chunk with row&7
__device__ __forceinline__ uint32_t sw256(int row, int k) {
    int ch = k >> 3;
    int swc = ((ch & 7) ^ (row & 7)) | (ch & 8);
    return row * 256 + ((swc << 4) | ((k & 7) * 2));
}

__device__ __forceinline__ void cvt8_regs(float4 v0, float4 v1, uint32_t* o) {
    __half2 h0 = __floats2half2_rn(v0.x, v0.y);
    __half2 h1 = __floats2half2_rn(v0.z, v0.w);
    __half2 h2 = __floats2half2_rn(v1.x, v1.y);
    __half2 h3 = __floats2half2_rn(v1.z, v1.w);
    o[0] = *reinterpret_cast<uint32_t*>(&h0);
    o[1] = *reinterpret_cast<uint32_t*>(&h1);
    o[2] = *reinterpret_cast<uint32_t*>(&h2);
    o[3] = *reinterpret_cast<uint32_t*>(&h3);
}

// ---------------- pre-pass: weights only ----------------
__global__ void __launch_bounds__(256)
prep_weights(const float* __restrict__ W_gd, const float* __restrict__ W_tau)
{
    int idx = blockIdx.x * 256 + threadIdx.x;   // 114688 + 32768
    const float* src; __half* dst;
    if (idx < 114688) {
        int row = idx / 112;
        int j = (idx - row * 112) * 8;
        src = &W_gd[(size_t)row * KTOT + j];
        dst = &g_wgd[(size_t)row * KTOT + j];
    } else {
        int e = idx - 114688;
        int row = e >> 6;
        int j = (e & 63) * 8;
        src = &W_tau[(size_t)row * HID + j];
        dst = &g_wtau[(size_t)row * HID + j];
    }
    float4 v0 = *reinterpret_cast<const float4*>(src);
    float4 v1 = *reinterpret_cast<const float4*>(src + 4);
    uint32_t o[4];
    cvt8_regs(v0, v1, o);
    uint4 u; u.x = o[0]; u.y = o[1]; u.z = o[2]; u.w = o[3];
    *reinterpret_cast<uint4*>(dst) = u;
}

// ---------------- main kernel ----------------
__global__ void __launch_bounds__(NTH, 1)
ltc_f16_kernel(const float* __restrict__ h_ltc, const float* __restrict__ x_t,
               const float* __restrict__ context,
               const float* __restrict__ b_gd, const float* __restrict__ b_tau,
               const float* __restrict__ gleak, const float* __restrict__ cm,
               float* __restrict__ out)
{
    extern __shared__ char smem[];
    const uint32_t data = (s2u(smem) + 127) & ~127u;

    const int tid  = threadIdx.x;
    const int wid  = tid >> 5;
    const int lane = tid & 31;
    const int m0 = blockIdx.y * BM;
    const int n0 = blockIdx.x * BN;

    const int wm = (wid & 3) * 32;
    const int wn = (wid >> 2) * 16;

    const int a_row = ((lane >> 3) & 1) * 8 + (lane & 7);
    const int a_k   = ((lane >> 4) & 1) * 8;
    const int b_row = ((lane >> 4) & 1) * 8 + (lane & 7);
    const int b_k   = ((lane >> 3) & 1) * 8;

    uint32_t aoff[2][4], bgof[4];
#pragma unroll
    for (int ks = 0; ks < 4; ++ks) {
#pragma unroll
        for (int mb = 0; mb < 2; ++mb)
            aoff[mb][ks] = sw256(wm + mb * 16 + a_row, ks * 16 + a_k);
        bgof[ks] = A_SZ + sw256(wn + b_row, ks * 16 + b_k);
    }

    // A loader: slot i = fp16 row r0+32i, 16B chunk ach
    const int r0  = tid >> 4;         // 0..31
    const int ach = tid & 15;
    uint32_t dAo[4];
#pragma unroll
    for (int i = 0; i < 4; ++i) dAo[i] = sw256(r0 + 32 * i, ach * 8);

    // B loader (cp.async from fp16 weight scratch)
    uint32_t dBo[2]; const __half *srcG[2], *srcD[2], *srcT[2];
#pragma unroll
    for (int i = 0; i < 2; ++i) {
        int s = tid + i * 512, r = s >> 4, ch = s & 15;
        dBo[i] = sw256(r, ch * 8);
        srcG[i] = g_wgd  + (size_t)(n0 + r) * KTOT + ch * 8;
        srcD[i] = g_wgd  + (size_t)(HID + n0 + r) * KTOT + ch * 8;
        srcT[i] = g_wtau + (size_t)(n0 + r) * HID + ch * 8;
    }

    // fp32 A source for chunk c (combined cols [c*128, (c+1)*128))
    auto a_base = [&](int c, int& stride) -> const float* {
        if (c == 0) { stride = IN_DIM; return x_t + (size_t)(m0 + r0) * IN_DIM + ach * 8; }
        if (c < 5)  { stride = HID;    return h_ltc + (size_t)(m0 + r0) * HID + (c - 1) * 128 + ach * 8; }
        stride = ATT; return context + (size_t)(m0 + r0) * ATT + (c - 5) * 128 + ach * 8;
    };

    float accg[2][2][4] = {}, accd[2][2][4] = {}, acct[2][2][4] = {};

    auto issue_B = [&](int c, uint32_t stn) {
#pragma unroll
        for (int i = 0; i < 2; ++i) {
            cp16(stn + A_SZ + dBo[i],        srcG[i] + c * KBLK);
            cp16(stn + A_SZ + B_SZ + dBo[i], srcD[i] + c * KBLK);
        }
        if (c >= 1 && c < 5) {
#pragma unroll
            for (int i = 0; i < 2; ++i)
                cp16(stn + A_SZ + 2 * B_SZ + dBo[i], srcT[i] + (c - 1) * KBLK);
        }
        cp_commit();
    };

    auto do_k8 = [&](int k8, uint32_t st, bool tau_act) {
        const int ks = k8 & 3;
        const uint32_t ext = (k8 >> 2) * 128;
        uint32_t a[2][4];
        ldm_x4(a[0], st + aoff[0][ks] + ext);
        ldm_x4(a[1], st + aoff[1][ks] + ext);
        uint32_t bg[4], bd[4], bt[4];
        const uint32_t bga = st + bgof[ks] + ext;
        ldm_x4(bg, bga);
        ldm_x4(bd, bga + B_SZ);
        if (tau_act) ldm_x4(bt, bga + 2 * B_SZ);
#pragma unroll
        for (int mb = 0; mb < 2; ++mb)
#pragma unroll
            for (int nb = 0; nb < 2; ++nb) {
                mma_f16(accg[mb][nb], a[mb], bg[nb * 2], bg[nb * 2 + 1]);
                mma_f16(accd[mb][nb], a[mb], bd[nb * 2], bd[nb * 2 + 1]);
            }
        if (tau_act) {
#pragma unroll
            for (int mb = 0; mb < 2; ++mb)
#pragma unroll
                for (int nb = 0; nb < 2; ++nb)
                    mma_f16(acct[mb][nb], a[mb], bt[nb * 2], bt[nb * 2 + 1]);
        }
    };

    // one chunk: compute on st; prefetch chunk cn into stn, A loads threaded
    // through the MMA stream (LDG slot i -> 2 k8 groups -> cvt+STS slot i)
    auto chunk_step = [&](uint32_t st, bool tau_act, bool pf, int cn, uint32_t stn) {
        const float* ab = nullptr; size_t rstep = 0;
        if (pf) {
            issue_B(cn, stn);
            int stride; ab = a_base(cn, stride);
            rstep = (size_t)32 * stride;
        }
        float4 v0, v1;
        if (pf) { v0 = *reinterpret_cast<const float4*>(ab);
                  v1 = *reinterpret_cast<const float4*>(ab + 4); }
        do_k8(0, st, tau_act);
        do_k8(1, st, tau_act);
        if (pf) {
            uint32_t o[4]; cvt8_regs(v0, v1, o); sts128(stn + dAo[0], o);
            v0 = *reinterpret_cast<const float4*>(ab + rstep);
            v1 = *reinterpret_cast<const float4*>(ab + rstep + 4);
        }
        do_k8(2, st, tau_act);
        do_k8(3, st, tau_act);
        if (pf) {
            uint32_t o[4]; cvt8_regs(v0, v1, o); sts128(stn + dAo[1], o);
            v0 = *reinterpret_cast<const float4*>(ab + 2 * rstep);
            v1 = *reinterpret_cast<const float4*>(ab + 2 * rstep + 4);
        }
        do_k8(4, st, tau_act);
        do_k8(5, st, tau_act);
        if (pf) {
            uint32_t o[4]; cvt8_regs(v0, v1, o); sts128(stn + dAo[2], o);
            v0 = *reinterpret_cast<const float4*>(ab + 3 * rstep);
            v1 = *reinterpret_cast<const float4*>(ab + 3 * rstep + 4);
        }
        do_k8(6, st, tau_act);
        do_k8(7, st, tau_act);
        if (pf) {
            uint32_t o[4]; cvt8_regs(v0, v1, o); sts128(stn + dAo[3], o);
            cp_wait<0>();
        }
        __syncthreads();
    };

    const uint32_t st0 = data;
    const uint32_t st1 = data + STAGE_BYTES;

    // ---- prologue: fill stage 0 with chunk 0 (one exposed A fill) ----
    issue_B(0, st0);
    {
        int stride; const float* ab = a_base(0, stride);
        const size_t rstep = (size_t)32 * stride;
#pragma unroll
        for (int i = 0; i < 4; ++i) {
            float4 v0 = *reinterpret_cast<const float4*>(ab + i * rstep);
            float4 v1 = *reinterpret_cast<const float4*>(ab + i * rstep + 4);
            uint32_t o[4]; cvt8_regs(v0, v1, o);
            sts128(st0 + dAo[i], o);
        }
    }
    cp_wait<0>();
    __syncthreads();

    // chunks: c=0 (x_t), 1..4 (h_ltc, tau), 5,6 (context). stage = c&1.
    chunk_step(st0, false, true, 1, st1);   // c=0
    chunk_step(st1, true,  true, 2, st0);   // c=1
    chunk_step(st0, true,  true, 3, st1);   // c=2
    chunk_step(st1, true,  true, 4, st0);   // c=3
    chunk_step(st0, true,  true, 5, st1);   // c=4
    chunk_step(st1, false, true, 6, st0);   // c=5
    chunk_step(st0, false, false, 0, st1);  // c=6

    // ---- fused epilogue (fast math) ----
    const int g  = lane >> 2;
    const int c2 = (lane & 3) * 2;
#pragma unroll
    for (int mb = 0; mb < 2; ++mb)
#pragma unroll
        for (int nb = 0; nb < 2; ++nb) {
            const int n = n0 + wn + nb * 8 + c2;
            const float bg0 = __ldg(&b_gd[n]),        bg1 = __ldg(&b_gd[n + 1]);
            const float bd0 = __ldg(&b_gd[n + HID]),  bd1 = __ldg(&b_gd[n + HID + 1]);
            const float bt0 = __ldg(&b_tau[n]),       bt1 = __ldg(&b_tau[n + 1]);
            const float dc0 = softplus_fast(__ldg(&cm[n]))   + softplus_fast(__ldg(&gleak[n]))   + 1e-6f;
            const float dc1 = softplus_fast(__ldg(&cm[n+1])) + softplus_fast(__ldg(&gleak[n+1])) + 1e-6f;
#pragma unroll
            for (int h = 0; h < 2; ++h) {
                const int m = m0 + wm + mb * 16 + h * 8 + g;
                const float2 hl = *reinterpret_cast<const float2*>(&h_ltc[(size_t)m * HID + n]);

                float gate0 = accg[mb][nb][h * 2 + 0] + bg0;
                float gate1 = accg[mb][nb][h * 2 + 1] + bg1;
                float dyn0  = accd[mb][nb][h * 2 + 0] + bd0;
                float dyn1  = accd[mb][nb][h * 2 + 1] + bd1;
                float tau0  = softplus_fast(acct[mb][nb][h * 2 + 0] + bt0);
                float tau1  = softplus_fast(acct[mb][nb][h * 2 + 1] + bt1);

                float r0v = __fdividef(sigmoid_fast(gate0) * tanh_fast(dyn0) - hl.x, tau0 + dc0);
                float r1v = __fdividef(sigmoid_fast(gate1) * tanh_fast(dyn1) - hl.y, tau1 + dc1);

                float2 o; o.x = r0v; o.y = r1v;
                *reinterpret_cast<float2*>(&out[(size_t)m * HID + n]) = o;
            }
        }
}

extern "C" void kernel_launch(void* const* d_in, const int* in_sizes, int n_in,
                              void* d_out, int out_size)
{
    // input order: t, h_ltc, x_t, context, W_gd, b_gd, W_tau, b_tau, gleak, cm
    const float* h_ltc   = (const float*)d_in[1];
    const float* x_t     = (const float*)d_in[2];
    const float* context = (const float*)d_in[3];
    const float* W_gd    = (const float*)d_in[4];
    const float* b_gd    = (const float*)d_in[5];
    const float* W_tau   = (const float*)d_in[6];
    const float* b_tau   = (const float*)d_in[7];
    const float* gleak   = (const float*)d_in[8];
    const float* cm      = (const float*)d_in[9];
    float* out = (float*)d_out;

    cudaFuncSetAttribute(ltc_f16_kernel,
                         cudaFuncAttributeMaxDynamicSharedMemorySize, SMEM_DYN);

    prep_weights<<<576, 256>>>(W_gd, W_tau);

    dim3 grid(HID / BN, BROWS / BM);   // (8, 128)
    ltc_f16_kernel<<<grid, NTH, SMEM_DYN>>>(h_ltc, x_t, context,
                                            b_gd, b_tau, gleak, cm, out);
}